// round 11
// baseline (speedup 1.0000x reference)
#include <cuda_runtime.h>
#include <cuda_fp16.h>
#include <math.h>

#define NN 150000
#define NE 1250000
#define NG 4096
#define HID 64

#define PS_B 512
#define PS_NB ((NN + PS_B - 1) / PS_B)   // 293

// Scratch (__device__ globals; no allocation allowed)
__device__ __align__(256) float  g_dinv[NN];
__device__ __align__(256) int    g_indeg[NN];
__device__ __align__(256) int    g_off[NN + 1];   // block-LOCAL exclusive offsets
__device__ __align__(256) int    g_cursor[NN];    // block-LOCAL cursors
__device__ __align__(256) int    g_bsum[PS_NB + 1]; // exclusive block offsets; [PS_NB]=NE
__device__ __align__(256) int2   g_edges[NE];     // {src, coef bits}, bucketed by dst
__device__ __align__(256) __half g_T0[NN * HID];  // h ping (fp16)
__device__ __align__(256) __half g_T1[NN * HID];  // h pong (fp16)
__device__ __align__(256) float  g_pool[NG * HID];
__device__ __align__(256) float  g_cnt[NG];

__device__ __forceinline__ void red_add_v4(float* addr, float4 v) {
    asm volatile("red.global.add.v4.f32 [%0], {%1,%2,%3,%4};"
                 :: "l"(addr), "f"(v.x), "f"(v.y), "f"(v.z), "f"(v.w)
                 : "memory");
}

// ---------------- degree ----------------
__global__ void k_deg_accum(const int* __restrict__ ei) {
    int e = blockIdx.x * blockDim.x + threadIdx.x;
    if (e < NE) atomicAdd(&g_indeg[ei[NE + e]], 1);
}

// ---------------- CSR scan phase 1: local scan + dinv ----------------
__global__ void k_ps1() {
    __shared__ int sh[PS_B];
    int tid = threadIdx.x;
    int i = blockIdx.x * PS_B + tid;
    int v = (i < NN) ? g_indeg[i] : 0;
    if (i < NN) g_dinv[i] = rsqrtf((float)(v + 1));   // fused deg_fin
    sh[tid] = v;
    __syncthreads();
    for (int o = 1; o < PS_B; o <<= 1) {
        int t2 = (tid >= o) ? sh[tid - o] : 0;
        __syncthreads();
        sh[tid] += t2;
        __syncthreads();
    }
    if (i <= NN) g_off[i] = sh[tid] - v;           // local exclusive (incl. slot NN)
    if (i < NN) g_cursor[i] = sh[tid] - v;
    if (tid == PS_B - 1) g_bsum[blockIdx.x] = sh[tid];
}
// ---------------- CSR scan phase 2: block offsets (exclusive) ----------------
__global__ void k_ps2() {
    __shared__ int sh[PS_B];
    int tid = threadIdx.x;
    int v = (tid < PS_NB) ? g_bsum[tid] : 0;
    sh[tid] = v;
    __syncthreads();
    for (int o = 1; o < PS_B; o <<= 1) {
        int t2 = (tid >= o) ? sh[tid - o] : 0;
        __syncthreads();
        sh[tid] += t2;
        __syncthreads();
    }
    if (tid < PS_NB) g_bsum[tid] = sh[tid] - v;    // exclusive
    if (tid == PS_NB - 1) g_bsum[PS_NB] = sh[tid]; // total = NE
}
// ---------------- bucket fill (local cursor + block base) ----------------
__global__ void k_fill(const int* __restrict__ ei) {
    int e = blockIdx.x * blockDim.x + threadIdx.x;
    if (e >= NE) return;
    int s = ei[e];
    int d = ei[NE + e];
    float coef = g_dinv[s] * g_dinv[d];
    int pos = atomicAdd(&g_cursor[d], 1) + __ldg(&g_bsum[d >> 9]);
    g_edges[pos] = make_int2(s, __float_as_int(coef));
}

// node's global edge range
__device__ __forceinline__ void node_range(int node, int& beg, int& end) {
    beg = __ldg(&g_off[node])     + __ldg(&g_bsum[node >> 9]);
    end = __ldg(&g_off[node + 1]) + __ldg(&g_bsum[(node + 1) >> 9]);
}

// ---------------- store 4 fp32 as 4 fp16 (8B) ----------------
__device__ __forceinline__ void store_h4(__half* dst, float4 v) {
    __half2 lo = __floats2half2_rn(v.x, v.y);
    __half2 hi = __floats2half2_rn(v.z, v.w);
    uint2 raw;
    raw.x = *(unsigned*)&lo;
    raw.y = *(unsigned*)&hi;
    *(uint2*)dst = raw;
}

// ---------------- layer 1: aggregate raw x (2ch), fused W1+bias+relu -> fp16 ----------------
__global__ void k_aggr_x(const float* __restrict__ x, const float* __restrict__ W1,
                         const float* __restrict__ b1, __half* __restrict__ hout) {
    __shared__ float W1s[2 * HID];
    __shared__ float b1s[HID];
    int tid = threadIdx.x;
    if (tid < 2 * HID) W1s[tid] = W1[tid];
    if (tid < HID) b1s[tid] = b1[tid];
    __syncthreads();
    int gt = blockIdx.x * blockDim.x + tid;
    int node = gt >> 4, q = gt & 15;
    if (node >= NN) return;
    int beg, end;
    node_range(node, beg, end);
    float s0 = 0.f, s1 = 0.f;
    int k = beg + q;
    for (; k + 48 < end; k += 64) {
        int2 p0 = __ldg(&g_edges[k]);
        int2 p1 = __ldg(&g_edges[k + 16]);
        int2 p2 = __ldg(&g_edges[k + 32]);
        int2 p3 = __ldg(&g_edges[k + 48]);
        float2 x0 = *(const float2*)(x + 2 * p0.x);
        float2 x1 = *(const float2*)(x + 2 * p1.x);
        float2 x2 = *(const float2*)(x + 2 * p2.x);
        float2 x3 = *(const float2*)(x + 2 * p3.x);
        s0 += __int_as_float(p0.y) * x0.x; s1 += __int_as_float(p0.y) * x0.y;
        s0 += __int_as_float(p1.y) * x1.x; s1 += __int_as_float(p1.y) * x1.y;
        s0 += __int_as_float(p2.y) * x2.x; s1 += __int_as_float(p2.y) * x2.y;
        s0 += __int_as_float(p3.y) * x3.x; s1 += __int_as_float(p3.y) * x3.y;
    }
    for (; k < end; k += 16) {
        int2 p = __ldg(&g_edges[k]);
        float c = __int_as_float(p.y);
        float2 xv = *(const float2*)(x + 2 * p.x);
        s0 += c * xv.x; s1 += c * xv.y;
    }
#pragma unroll
    for (int o = 8; o; o >>= 1) {
        s0 += __shfl_xor_sync(0xffffffffu, s0, o, 16);
        s1 += __shfl_xor_sync(0xffffffffu, s1, o, 16);
    }
    float di = g_dinv[node];
    float d2 = di * di;
    s0 += x[2 * node] * d2;
    s1 += x[2 * node + 1] * d2;
    int c0 = q * 4;
    float4 r;
    r.x = fmaxf(s0 * W1s[c0 + 0] + s1 * W1s[HID + c0 + 0] + b1s[c0 + 0], 0.f);
    r.y = fmaxf(s0 * W1s[c0 + 1] + s1 * W1s[HID + c0 + 1] + b1s[c0 + 1], 0.f);
    r.z = fmaxf(s0 * W1s[c0 + 2] + s1 * W1s[HID + c0 + 2] + b1s[c0 + 2], 0.f);
    r.w = fmaxf(s0 * W1s[c0 + 3] + s1 * W1s[HID + c0 + 3] + b1s[c0 + 3], 0.f);
    store_h4(hout + (size_t)node * HID + c0, r);
}

// ---------------- fp16 row gather ----------------
__device__ __forceinline__ float4 gather_h4(const __half* __restrict__ t, int row, int q) {
    uint2 raw = __ldg((const uint2*)(t + ((size_t)row << 6) + (q << 2)));
    float2 a = __half22float2(*(__half2*)&raw.x);
    float2 b = __half22float2(*(__half2*)&raw.y);
    return make_float4(a.x, a.y, b.x, b.y);
}

#define ACC4(c, v) { acc.x += (c) * (v).x; acc.y += (c) * (v).y; \
                     acc.z += (c) * (v).z; acc.w += (c) * (v).w; }

// Aggregation core, unrolled x4: u = agg_edges(h) + h[node]*dinv^2.
__device__ __forceinline__ float4 agg_core(const __half* __restrict__ t, int node, int q) {
    float di = g_dinv[node];
    float d2 = di * di;
    float4 acc = gather_h4(t, node, q);
    acc.x *= d2; acc.y *= d2; acc.z *= d2; acc.w *= d2;
    int beg, end;
    node_range(node, beg, end);
    int k = beg;
    for (; k + 4 <= end; k += 4) {
        int2 p0 = __ldg(&g_edges[k]);
        int2 p1 = __ldg(&g_edges[k + 1]);
        int2 p2 = __ldg(&g_edges[k + 2]);
        int2 p3 = __ldg(&g_edges[k + 3]);
        float4 v0 = gather_h4(t, p0.x, q);
        float4 v1 = gather_h4(t, p1.x, q);
        float4 v2 = gather_h4(t, p2.x, q);
        float4 v3 = gather_h4(t, p3.x, q);
        ACC4(__int_as_float(p0.y), v0); ACC4(__int_as_float(p1.y), v1);
        ACC4(__int_as_float(p2.y), v2); ACC4(__int_as_float(p3.y), v3);
    }
    for (; k < end; k++) {
        int2 p = __ldg(&g_edges[k]);
        float c = __int_as_float(p.y);
        float4 v = gather_h4(t, p.x, q);
        ACC4(c, v);
    }
    return acc;
}

// Warp-level 64x64 matmul: per-node h lives in 16 lanes' float4; broadcast via shfl.
__device__ __forceinline__ float4 warp_matmul(float4 acc, const float* __restrict__ Ws,
                                              const float* __restrict__ bs, int q) {
    float a[4] = {acc.x, acc.y, acc.z, acc.w};
    int c0 = q * 4;
    float4 o = make_float4(bs[c0], bs[c0 + 1], bs[c0 + 2], bs[c0 + 3]);
#pragma unroll
    for (int k = 0; k < HID; k++) {
        float hk = __shfl_sync(0xffffffffu, a[k & 3], k >> 2, 16);
        float4 w = *(const float4*)&Ws[k * HID + c0];
        o.x += hk * w.x; o.y += hk * w.y; o.z += hk * w.z; o.w += hk * w.w;
    }
    o.x = fmaxf(o.x, 0.f); o.y = fmaxf(o.y, 0.f);
    o.z = fmaxf(o.z, 0.f); o.w = fmaxf(o.w, 0.f);
    return o;
}

// ---------------- fused layer: out = relu((agg(h) + h*dinv^2) @ W + b) ----------------
// 256 threads = 16 nodes x 16 lanes; launch_bounds caps regs for >=4 blocks/SM.
__global__ void __launch_bounds__(256, 4) k_layer(const __half* __restrict__ tin,
                                                  const float* __restrict__ W,
                                                  const float* __restrict__ b,
                                                  __half* __restrict__ tout) {
    __shared__ float Ws[HID * HID];
    __shared__ float bs[HID];
    int tid = threadIdx.x;
    for (int i = tid; i < HID * HID; i += 256) Ws[i] = W[i];
    if (tid < HID) bs[tid] = b[tid];
    __syncthreads();
    int q = tid & 15;
    int node = blockIdx.x * 16 + (tid >> 4);
    if (node >= NN) return;
    float4 acc = agg_core(tin, node, q);
    float4 o = warp_matmul(acc, Ws, bs, q);
    store_h4(tout + (size_t)node * HID + q * 4, o);
}

// Layer-3 variant: epilogue goes straight into the mean-pool accumulators.
__global__ void __launch_bounds__(256, 4) k_layer_pool(const __half* __restrict__ tin,
                                                        const float* __restrict__ W,
                                                        const float* __restrict__ b,
                                                        const int* __restrict__ batch) {
    __shared__ float Ws[HID * HID];
    __shared__ float bs[HID];
    int tid = threadIdx.x;
    for (int i = tid; i < HID * HID; i += 256) Ws[i] = W[i];
    if (tid < HID) bs[tid] = b[tid];
    __syncthreads();
    int q = tid & 15;
    int node = blockIdx.x * 16 + (tid >> 4);
    if (node >= NN) return;
    float4 acc = agg_core(tin, node, q);
    float4 o = warp_matmul(acc, Ws, bs, q);
    int g = batch[node];
    red_add_v4(g_pool + (size_t)g * HID + q * 4, o);
    if (q == 0) atomicAdd(&g_cnt[g], 1.0f);
}

// ---------------- per-graph MLP + sigmoid ----------------
__global__ void k_mlp(const float* __restrict__ lw1, const float* __restrict__ lb1,
                      const float* __restrict__ lw2, const float* __restrict__ lb2,
                      float* __restrict__ out) {
    __shared__ float w1s[HID * 32];
    __shared__ float b1s[32];
    __shared__ float w2s[32];
    int tid = threadIdx.x;
    for (int idx = tid; idx < HID * 32; idx += 128) w1s[idx] = lw1[idx];
    if (tid < 32) { b1s[tid] = lb1[tid]; w2s[tid] = lw2[tid]; }
    __syncthreads();
    int g = blockIdx.x * 128 + tid;
    if (g >= NG) return;
    float inv = 1.0f / fmaxf(g_cnt[g], 1.0f);
    float p[HID];
#pragma unroll
    for (int c = 0; c < HID; c++) p[c] = g_pool[g * HID + c] * inv;
    float z = lb2[0];
    for (int j = 0; j < 32; j++) {
        float a = b1s[j];
#pragma unroll
        for (int c = 0; c < HID; c++) a += p[c] * w1s[c * 32 + j];
        a = a > 0.f ? a : 0.f;
        z += a * w2s[j];
    }
    out[g] = 1.0f / (1.0f + expf(-z));
}

extern "C" void kernel_launch(void* const* d_in, const int* in_sizes, int n_in,
                              void* d_out, int out_size) {
    // Size-driven input identification (robust to metadata ordering).
    const float *x = 0, *W1 = 0, *b1 = 0, *W2 = 0, *b2 = 0, *W3 = 0, *b3 = 0;
    const float *lw1 = 0, *lb1 = 0, *lw2 = 0, *lb2 = 0;
    const int *ei = 0, *batch = 0;
    int nW = 0, nb = 0, n32 = 0;
    for (int i = 0; i < n_in; i++) {
        int sz = in_sizes[i];
        const void* p = d_in[i];
        switch (sz) {
            case 300000:  x = (const float*)p; break;
            case 2500000: ei = (const int*)p; break;
            case 150000:  batch = (const int*)p; break;
            case 128:     W1 = (const float*)p; break;
            case 4096:    if (nW++ == 0) W2 = (const float*)p; else W3 = (const float*)p; break;
            case 64:      if (nb == 0) b1 = (const float*)p;
                          else if (nb == 1) b2 = (const float*)p;
                          else b3 = (const float*)p;
                          nb++; break;
            case 2048:    lw1 = (const float*)p; break;
            case 32:      if (n32++ == 0) lb1 = (const float*)p; else lw2 = (const float*)p; break;
            case 1:       lb2 = (const float*)p; break;
        }
    }
    float* out = (float*)d_out;

    __half *gT0, *gT1;
    float *gPool, *gCnt;
    int *gIndeg;
    cudaGetSymbolAddress((void**)&gT0, g_T0);
    cudaGetSymbolAddress((void**)&gT1, g_T1);
    cudaGetSymbolAddress((void**)&gPool, g_pool);
    cudaGetSymbolAddress((void**)&gCnt, g_cnt);
    cudaGetSymbolAddress((void**)&gIndeg, g_indeg);

    const int TB = 256;
    // zeroing via memset nodes (no kernel-launch overhead)
    cudaMemsetAsync(gIndeg, 0, NN * sizeof(int));
    cudaMemsetAsync(gPool, 0, NG * HID * sizeof(float));
    cudaMemsetAsync(gCnt, 0, NG * sizeof(float));

    // degree + CSR build (dst-bucketed, packed {src, coef})
    k_deg_accum<<<(NE + TB - 1) / TB, TB>>>(ei);
    k_ps1 <<<PS_NB, PS_B>>>();
    k_ps2 <<<1, PS_B>>>();
    k_fill<<<(NE + TB - 1) / TB, TB>>>(ei);

    // layer 1: aggregate raw x, fused W1+bias+relu -> h1 (fp16)
    k_aggr_x<<<(NN * 16 + TB - 1) / TB, TB>>>(x, W1, b1, gT0);

    // layer 2 fused: h2 = relu((agg(h1)+h1*d2) @ W2 + b2) (fp16)
    k_layer<<<(NN + 15) / 16, TB>>>(gT0, W2, b2, gT1);

    // layer 3 fused + pooled
    k_layer_pool<<<(NN + 15) / 16, TB>>>(gT1, W3, b3, batch);

    // MLP head
    k_mlp<<<(NG + 127) / 128, 128>>>(lw1, lb1, lw2, lb2, out);
}

// round 14
// speedup vs baseline: 1.1516x; 1.1516x over previous
#include <cuda_runtime.h>
#include <cuda_fp16.h>
#include <math.h>

#define NN 150000
#define NE 1250000
#define NG 4096
#define HID 64

#define PS_B 512
#define PS_NB ((NN + PS_B - 1) / PS_B)   // 293

// Scratch (__device__ globals; no allocation allowed)
__device__ __align__(256) float  g_dinv[NN];
__device__ __align__(256) float2 g_xs[NN];        // x' = x * dinv (pre-scaled input)
__device__ __align__(256) int    g_indeg[NN];
__device__ __align__(256) int    g_off[NN + 1];   // global exclusive offsets
__device__ __align__(256) int    g_cursor[NN];
__device__ __align__(256) int    g_bsum[PS_NB];
__device__ __align__(256) int    g_edges[NE];     // src only (4B), bucketed by dst
__device__ __align__(256) __half g_T0[NN * HID];  // h' = h*dinv ping (fp16)
__device__ __align__(256) __half g_T1[NN * HID];  // h' pong (fp16)
__device__ __align__(256) float  g_pool[NG * HID];
__device__ __align__(256) float  g_cnt[NG];

__device__ __forceinline__ void red_add_v4(float* addr, float4 v) {
    asm volatile("red.global.add.v4.f32 [%0], {%1,%2,%3,%4};"
                 :: "l"(addr), "f"(v.x), "f"(v.y), "f"(v.z), "f"(v.w)
                 : "memory");
}

// ---------------- degree ----------------
__global__ void k_deg_accum(const int* __restrict__ ei) {
    int e = blockIdx.x * blockDim.x + threadIdx.x;
    if (e < NE) atomicAdd(&g_indeg[ei[NE + e]], 1);
}

// ---------------- CSR scan 1: local scan + dinv + x' precompute ----------------
__global__ void k_ps1(const float* __restrict__ x) {
    __shared__ int sh[PS_B];
    int tid = threadIdx.x;
    int i = blockIdx.x * PS_B + tid;
    int v = (i < NN) ? g_indeg[i] : 0;
    if (i < NN) {
        float di = rsqrtf((float)(v + 1));
        g_dinv[i] = di;
        float2 xv = *(const float2*)(x + 2 * i);
        g_xs[i] = make_float2(xv.x * di, xv.y * di);
    }
    sh[tid] = v;
    __syncthreads();
    for (int o = 1; o < PS_B; o <<= 1) {
        int t2 = (tid >= o) ? sh[tid - o] : 0;
        __syncthreads();
        sh[tid] += t2;
        __syncthreads();
    }
    if (i < NN) g_off[i] = sh[tid] - v;            // local exclusive
    if (tid == PS_B - 1) g_bsum[blockIdx.x] = sh[tid];
}
__global__ void k_ps2() {
    __shared__ int sh[PS_B];
    int tid = threadIdx.x;
    int v = (tid < PS_NB) ? g_bsum[tid] : 0;
    sh[tid] = v;
    __syncthreads();
    for (int o = 1; o < PS_B; o <<= 1) {
        int t2 = (tid >= o) ? sh[tid - o] : 0;
        __syncthreads();
        sh[tid] += t2;
        __syncthreads();
    }
    if (tid < PS_NB) g_bsum[tid] = sh[tid] - v;    // exclusive block offsets
}
__global__ void k_ps3() {
    int i = blockIdx.x * PS_B + threadIdx.x;
    if (i < NN) {
        int o = g_off[i] + g_bsum[blockIdx.x];
        g_off[i] = o;
        g_cursor[i] = o;
    }
    if (i == 0) g_off[NN] = NE;
}
// ---------------- bucket fill: src only ----------------
__global__ void k_fill(const int* __restrict__ ei) {
    int e = blockIdx.x * blockDim.x + threadIdx.x;
    if (e >= NE) return;
    int s = ei[e];
    int d = ei[NE + e];
    int pos = atomicAdd(&g_cursor[d], 1);
    g_edges[pos] = s;
}

// ---------------- store 4 fp32 as 4 fp16 (8B) ----------------
__device__ __forceinline__ void store_h4(__half* dst, float4 v) {
    __half2 lo = __floats2half2_rn(v.x, v.y);
    __half2 hi = __floats2half2_rn(v.z, v.w);
    uint2 raw;
    raw.x = *(unsigned*)&lo;
    raw.y = *(unsigned*)&hi;
    *(uint2*)dst = raw;
}

// ---------------- layer 1: aggregate x' (2ch), fused W1+bias+relu, store h1*dinv ----------------
__global__ void k_aggr_x(const float* __restrict__ W1, const float* __restrict__ b1,
                         __half* __restrict__ hout) {
    __shared__ float W1s[2 * HID];
    __shared__ float b1s[HID];
    int tid = threadIdx.x;
    if (tid < 2 * HID) W1s[tid] = W1[tid];
    if (tid < HID) b1s[tid] = b1[tid];
    __syncthreads();
    int gt = blockIdx.x * blockDim.x + tid;
    int node = gt >> 4, q = gt & 15;
    if (node >= NN) return;
    int beg = __ldg(&g_off[node]), end = __ldg(&g_off[node + 1]);
    float s0 = 0.f, s1 = 0.f;
    int k = beg + q;
    for (; k + 48 < end; k += 64) {
        int p0 = __ldg(&g_edges[k]);
        int p1 = __ldg(&g_edges[k + 16]);
        int p2 = __ldg(&g_edges[k + 32]);
        int p3 = __ldg(&g_edges[k + 48]);
        float2 x0 = __ldg(&g_xs[p0]);
        float2 x1 = __ldg(&g_xs[p1]);
        float2 x2 = __ldg(&g_xs[p2]);
        float2 x3 = __ldg(&g_xs[p3]);
        s0 += x0.x + x1.x + x2.x + x3.x;
        s1 += x0.y + x1.y + x2.y + x3.y;
    }
    for (; k < end; k += 16) {
        float2 xv = __ldg(&g_xs[__ldg(&g_edges[k])]);
        s0 += xv.x; s1 += xv.y;
    }
#pragma unroll
    for (int o = 8; o; o >>= 1) {
        s0 += __shfl_xor_sync(0xffffffffu, s0, o, 16);
        s1 += __shfl_xor_sync(0xffffffffu, s1, o, 16);
    }
    float di = g_dinv[node];
    float2 xn = __ldg(&g_xs[node]);   // xn = x*di already
    // u = di*(S + x'[node])  =>  di*S + x*di^2  (correct self-loop)
    s0 = di * (s0 + xn.x);
    s1 = di * (s1 + xn.y);
    int c0 = q * 4;
    float4 r;
    r.x = fmaxf(s0 * W1s[c0 + 0] + s1 * W1s[HID + c0 + 0] + b1s[c0 + 0], 0.f);
    r.y = fmaxf(s0 * W1s[c0 + 1] + s1 * W1s[HID + c0 + 1] + b1s[c0 + 1], 0.f);
    r.z = fmaxf(s0 * W1s[c0 + 2] + s1 * W1s[HID + c0 + 2] + b1s[c0 + 2], 0.f);
    r.w = fmaxf(s0 * W1s[c0 + 3] + s1 * W1s[HID + c0 + 3] + b1s[c0 + 3], 0.f);
    // store h1' = h1 * dinv for next layer's gather
    r.x *= di; r.y *= di; r.z *= di; r.w *= di;
    store_h4(hout + (size_t)node * HID + c0, r);
}

// ---------------- fp16 row gather ----------------
__device__ __forceinline__ float4 gather_h4(const __half* __restrict__ t, int row, int q) {
    uint2 raw = __ldg((const uint2*)(t + ((size_t)row << 6) + (q << 2)));
    float2 a = __half22float2(*(__half2*)&raw.x);
    float2 b = __half22float2(*(__half2*)&raw.y);
    return make_float4(a.x, a.y, b.x, b.y);
}

#define ADD4(v) { acc.x += (v).x; acc.y += (v).y; acc.z += (v).z; acc.w += (v).w; }

// Aggregation core, unrolled x8: u = di*(sum t'[s] + t'[node]).
// (t'[node] = h*di, so self term = h*di^2 after the final *di. Correct.)
__device__ __forceinline__ float4 agg_core(const __half* __restrict__ t, int node, int q,
                                           float di) {
    float4 acc = gather_h4(t, node, q);      // t'[node], NO extra di here
    int beg = __ldg(&g_off[node]), end = __ldg(&g_off[node + 1]);
    int k = beg;
    for (; k + 8 <= end; k += 8) {
        int p0 = __ldg(&g_edges[k]);
        int p1 = __ldg(&g_edges[k + 1]);
        int p2 = __ldg(&g_edges[k + 2]);
        int p3 = __ldg(&g_edges[k + 3]);
        int p4 = __ldg(&g_edges[k + 4]);
        int p5 = __ldg(&g_edges[k + 5]);
        int p6 = __ldg(&g_edges[k + 6]);
        int p7 = __ldg(&g_edges[k + 7]);
        float4 v0 = gather_h4(t, p0, q);
        float4 v1 = gather_h4(t, p1, q);
        float4 v2 = gather_h4(t, p2, q);
        float4 v3 = gather_h4(t, p3, q);
        float4 v4 = gather_h4(t, p4, q);
        float4 v5 = gather_h4(t, p5, q);
        float4 v6 = gather_h4(t, p6, q);
        float4 v7 = gather_h4(t, p7, q);
        ADD4(v0); ADD4(v1); ADD4(v2); ADD4(v3);
        ADD4(v4); ADD4(v5); ADD4(v6); ADD4(v7);
    }
    if (k + 4 <= end) {
        int p0 = __ldg(&g_edges[k]);
        int p1 = __ldg(&g_edges[k + 1]);
        int p2 = __ldg(&g_edges[k + 2]);
        int p3 = __ldg(&g_edges[k + 3]);
        float4 v0 = gather_h4(t, p0, q);
        float4 v1 = gather_h4(t, p1, q);
        float4 v2 = gather_h4(t, p2, q);
        float4 v3 = gather_h4(t, p3, q);
        ADD4(v0); ADD4(v1); ADD4(v2); ADD4(v3);
        k += 4;
    }
    for (; k < end; k++) {
        float4 v = gather_h4(t, __ldg(&g_edges[k]), q);
        ADD4(v);
    }
    acc.x *= di; acc.y *= di; acc.z *= di; acc.w *= di;
    return acc;
}

// Warp-level 64x64 matmul: per-node u lives in 16 lanes' float4; broadcast via shfl.
__device__ __forceinline__ float4 warp_matmul(float4 acc, const float* __restrict__ Ws,
                                              const float* __restrict__ bs, int q) {
    float a[4] = {acc.x, acc.y, acc.z, acc.w};
    int c0 = q * 4;
    float4 o = make_float4(bs[c0], bs[c0 + 1], bs[c0 + 2], bs[c0 + 3]);
#pragma unroll
    for (int k = 0; k < HID; k++) {
        float hk = __shfl_sync(0xffffffffu, a[k & 3], k >> 2, 16);
        float4 w = *(const float4*)&Ws[k * HID + c0];
        o.x += hk * w.x; o.y += hk * w.y; o.z += hk * w.z; o.w += hk * w.w;
    }
    o.x = fmaxf(o.x, 0.f); o.y = fmaxf(o.y, 0.f);
    o.z = fmaxf(o.z, 0.f); o.w = fmaxf(o.w, 0.f);
    return o;
}

// ---------------- fused layer: out = relu(u @ W + b) * dinv (for next gather) ----------------
__global__ void __launch_bounds__(512) k_layer(const __half* __restrict__ tin,
                                               const float* __restrict__ W,
                                               const float* __restrict__ b,
                                               __half* __restrict__ tout) {
    __shared__ float Ws[HID * HID];
    __shared__ float bs[HID];
    int tid = threadIdx.x;
    for (int i = tid; i < HID * HID; i += 512) Ws[i] = W[i];
    if (tid < HID) bs[tid] = b[tid];
    __syncthreads();
    int q = tid & 15;
    int node = blockIdx.x * 32 + (tid >> 4);
    if (node >= NN) return;
    float di = g_dinv[node];
    float4 acc = agg_core(tin, node, q, di);
    float4 o = warp_matmul(acc, Ws, bs, q);
    o.x *= di; o.y *= di; o.z *= di; o.w *= di;   // pre-scale for next layer
    store_h4(tout + (size_t)node * HID + q * 4, o);
}

// Layer-3 variant: plain h into the mean-pool accumulators.
__global__ void __launch_bounds__(512) k_layer_pool(const __half* __restrict__ tin,
                                                    const float* __restrict__ W,
                                                    const float* __restrict__ b,
                                                    const int* __restrict__ batch) {
    __shared__ float Ws[HID * HID];
    __shared__ float bs[HID];
    int tid = threadIdx.x;
    for (int i = tid; i < HID * HID; i += 512) Ws[i] = W[i];
    if (tid < HID) bs[tid] = b[tid];
    __syncthreads();
    int q = tid & 15;
    int node = blockIdx.x * 32 + (tid >> 4);
    if (node >= NN) return;
    float di = g_dinv[node];
    float4 acc = agg_core(tin, node, q, di);
    float4 o = warp_matmul(acc, Ws, bs, q);
    int g = batch[node];
    red_add_v4(g_pool + (size_t)g * HID + q * 4, o);
    if (q == 0) atomicAdd(&g_cnt[g], 1.0f);
}

// ---------------- per-graph MLP + sigmoid ----------------
__global__ void k_mlp(const float* __restrict__ lw1, const float* __restrict__ lb1,
                      const float* __restrict__ lw2, const float* __restrict__ lb2,
                      float* __restrict__ out) {
    __shared__ float w1s[HID * 32];
    __shared__ float b1s[32];
    __shared__ float w2s[32];
    int tid = threadIdx.x;
    for (int idx = tid; idx < HID * 32; idx += 128) w1s[idx] = lw1[idx];
    if (tid < 32) { b1s[tid] = lb1[tid]; w2s[tid] = lw2[tid]; }
    __syncthreads();
    int g = blockIdx.x * 128 + tid;
    if (g >= NG) return;
    float inv = 1.0f / fmaxf(g_cnt[g], 1.0f);
    float p[HID];
#pragma unroll
    for (int c = 0; c < HID; c++) p[c] = g_pool[g * HID + c] * inv;
    float z = lb2[0];
    for (int j = 0; j < 32; j++) {
        float a = b1s[j];
#pragma unroll
        for (int c = 0; c < HID; c++) a += p[c] * w1s[c * 32 + j];
        a = a > 0.f ? a : 0.f;
        z += a * w2s[j];
    }
    out[g] = 1.0f / (1.0f + expf(-z));
}

extern "C" void kernel_launch(void* const* d_in, const int* in_sizes, int n_in,
                              void* d_out, int out_size) {
    // Size-driven input identification (robust to metadata ordering).
    const float *x = 0, *W1 = 0, *b1 = 0, *W2 = 0, *b2 = 0, *W3 = 0, *b3 = 0;
    const float *lw1 = 0, *lb1 = 0, *lw2 = 0, *lb2 = 0;
    const int *ei = 0, *batch = 0;
    int nW = 0, nb = 0, n32 = 0;
    for (int i = 0; i < n_in; i++) {
        int sz = in_sizes[i];
        const void* p = d_in[i];
        switch (sz) {
            case 300000:  x = (const float*)p; break;
            case 2500000: ei = (const int*)p; break;
            case 150000:  batch = (const int*)p; break;
            case 128:     W1 = (const float*)p; break;
            case 4096:    if (nW++ == 0) W2 = (const float*)p; else W3 = (const float*)p; break;
            case 64:      if (nb == 0) b1 = (const float*)p;
                          else if (nb == 1) b2 = (const float*)p;
                          else b3 = (const float*)p;
                          nb++; break;
            case 2048:    lw1 = (const float*)p; break;
            case 32:      if (n32++ == 0) lb1 = (const float*)p; else lw2 = (const float*)p; break;
            case 1:       lb2 = (const float*)p; break;
        }
    }
    float* out = (float*)d_out;

    __half *gT0, *gT1;
    float *gPool, *gCnt;
    int *gIndeg;
    cudaGetSymbolAddress((void**)&gT0, g_T0);
    cudaGetSymbolAddress((void**)&gT1, g_T1);
    cudaGetSymbolAddress((void**)&gPool, g_pool);
    cudaGetSymbolAddress((void**)&gCnt, g_cnt);
    cudaGetSymbolAddress((void**)&gIndeg, g_indeg);

    const int TB = 256;
    // zeroing via memset nodes (no kernel-launch overhead)
    cudaMemsetAsync(gIndeg, 0, NN * sizeof(int));
    cudaMemsetAsync(gPool, 0, NG * HID * sizeof(float));
    cudaMemsetAsync(gCnt, 0, NG * sizeof(float));

    // degree + CSR build (dst-bucketed, src-only records)
    k_deg_accum<<<(NE + TB - 1) / TB, TB>>>(ei);
    k_ps1 <<<PS_NB, PS_B>>>(x);
    k_ps2 <<<1, PS_B>>>();
    k_ps3 <<<PS_NB, PS_B>>>();
    k_fill<<<(NE + TB - 1) / TB, TB>>>(ei);

    // layer 1: aggregate x', fused W1+bias+relu -> h1' (fp16, pre-scaled)
    k_aggr_x<<<(NN * 16 + TB - 1) / TB, TB>>>(W1, b1, gT0);

    // layer 2 fused
    k_layer<<<(NN + 31) / 32, 512>>>(gT0, W2, b2, gT1);

    // layer 3 fused + pooled
    k_layer_pool<<<(NN + 31) / 32, 512>>>(gT1, W3, b3, batch);

    // MLP head
    k_mlp<<<(NG + 127) / 128, 128>>>(lw1, lb1, lw2, lb2, out);
}